// round 13
// baseline (speedup 1.0000x reference)
#include <cuda_runtime.h>
#include <cuda_fp16.h>
#include <cstdint>

#define NF    10240
#define CDIM  64      // B*DOUT = 4*16 packed batch-output columns
#define KSPLIT 5
#define KPER  (NF / KSPLIT)   // 2048
#define MTILE 128
#define KTILE 16
#define NSTAGES (KPER / KTILE)   // 128
#define NBUF  6
#define AS_PITCH_H 136   // halves per A16 smem row (R8-proven LDSM layout)
#define GS_PITCH_H 24    // halves per G smem row (R10-proven LDSM layout)
#define AS_BYTES (KTILE * AS_PITCH_H * 2)   // 4352
#define GS_BYTES (CDIM * GS_PITCH_H * 2)    // 3072
#define BUF_BYTES (AS_BYTES + GS_BYTES)     // 7424
#define SMEM_TOTAL (NBUF * BUF_BYTES)       // 44544 -> 4 CTAs/SM (reg-capped)

// -------- device scratch (allocation-free rule: static __device__ arrays) ----
__device__ __align__(256) __half g_A16[(size_t)NF * NF];  // supports fp16 (210 MB)
__device__ __align__(256) float  g_H0T[CDIM * NF];        // H0^T fp32 [c][i]
__device__ __align__(256) float  g_degPart[80 * NF];
__device__ float  g_dinv[NF];
__device__ float  g_diagfix[NF];
__device__ __align__(256) __half g_GT[CDIM * NF];         // G^T fp16 [c][i]
__device__ __align__(256) float  g_Ppart[KSPLIT * NF * CDIM];

// ---------------- K1: deg partials + fp16 convert (single wave: 800 CTAs) ----
// Reads S once (400MB), writes g_A16 (200MB, streaming), deg column partials.
__global__ __launch_bounds__(256, 6) void k1_a16_deg(const float* __restrict__ S) {
    int j4 = blockIdx.x * 1024 + threadIdx.x * 4;
    int k0 = blockIdx.y * 128;
    const float* p = S + (size_t)k0 * NF + j4;
    __half* q = g_A16 + (size_t)k0 * NF + j4;
    float4 acc = make_float4(0.f, 0.f, 0.f, 0.f);
    #pragma unroll 4
    for (int it = 0; it < 128; ++it) {
        float4 v = *reinterpret_cast<const float4*>(p);
        acc.x += v.x; acc.y += v.y; acc.z += v.z; acc.w += v.w;
        __half2 h01 = __floats2half2_rn(v.x, v.y);
        __half2 h23 = __floats2half2_rn(v.z, v.w);
        uint2 w;
        w.x = *reinterpret_cast<uint32_t*>(&h01);
        w.y = *reinterpret_cast<uint32_t*>(&h23);
        __stcs(reinterpret_cast<uint2*>(q), w);   // streaming store
        p += NF; q += NF;
    }
    *reinterpret_cast<float4*>(&g_degPart[blockIdx.y * NF + j4]) = acc;
}

// ------------------------------------------------------- K2a: dinv + diagfix --
__global__ void k2a_dinv(const float* __restrict__ S) {
    int j = blockIdx.x * 256 + threadIdx.x;
    float s = 0.f;
    #pragma unroll 8
    for (int r = 0; r < 80; ++r) s += g_degPart[r * NF + j];
    float dv  = S[(size_t)j * NF + j];
    float fix = (dv == 0.0f) ? 1.0f : 0.0f;   // add_remaining_self_loops
    s += fix;
    g_diagfix[j] = fix;
    g_dinv[j] = (s > 0.f) ? rsqrtf(s) : 0.f;
}

// ------------------------------------- K0b: H0^T (fp32) + G^T (fp16, fused) --
__global__ void k0b_h0_gt(const float* __restrict__ x, const float* __restrict__ Wg) {
    __shared__ float W[256];
    if (threadIdx.x < 256) W[threadIdx.x] = Wg[threadIdx.x];
    __syncthreads();
    int i = blockIdx.x * 256 + threadIdx.x;
    float dv = g_dinv[i];
    #pragma unroll
    for (int b = 0; b < 4; ++b) {
        float xv[16];
        const float4* px = reinterpret_cast<const float4*>(x + ((size_t)b * NF + i) * 16);
        #pragma unroll
        for (int qd = 0; qd < 4; ++qd) {
            float4 v = px[qd];
            xv[qd*4+0] = v.x; xv[qd*4+1] = v.y; xv[qd*4+2] = v.z; xv[qd*4+3] = v.w;
        }
        #pragma unroll
        for (int o = 0; o < 16; ++o) {
            float s = 0.f;
            #pragma unroll
            for (int d = 0; d < 16; ++d) s += xv[d] * W[d * 16 + o];
            int c = b * 16 + o;
            g_H0T[c * NF + i] = s;
            g_GT[c * NF + i]  = __float2half_rn(dv * s);
        }
    }
}

// --------------------------------------------------------------- K3: GEMM ----
// P[j,c] = sum_i A[i,j]*G[i,c]; fp16 A via LDSM.trans (R8-proven), G via LDSM.
// 6-buf ring, one sync per stage, 4 CTAs/SM, single wave (400 CTAs).
__device__ __forceinline__ void cp_async16(uint32_t dst, const void* src) {
    asm volatile("cp.async.cg.shared.global [%0], [%1], 16;\n" :: "r"(dst), "l"(src));
}
#define CP_COMMIT() asm volatile("cp.async.commit_group;\n" ::: "memory")
#define CP_WAIT(n)  asm volatile("cp.async.wait_group %0;\n" :: "n"(n) : "memory")
#define LDSM_X4(r0,r1,r2,r3,a) \
    asm volatile("ldmatrix.sync.aligned.m8n8.x4.shared.b16 {%0,%1,%2,%3},[%4];" \
        : "=r"(r0),"=r"(r1),"=r"(r2),"=r"(r3) : "r"(a))
#define LDSM_X4_T(r0,r1,r2,r3,a) \
    asm volatile("ldmatrix.sync.aligned.m8n8.x4.trans.shared.b16 {%0,%1,%2,%3},[%4];" \
        : "=r"(r0),"=r"(r1),"=r"(r2),"=r"(r3) : "r"(a))

__global__ __launch_bounds__(256, 4) void k3_gemm() {
    extern __shared__ char smem[];
    const uint32_t sbase = (uint32_t)__cvta_generic_to_shared(smem);

    const int tid  = threadIdx.x;
    const int warp = tid >> 5;
    const int lane = tid & 31;
    const int g    = lane >> 2;
    const int t4   = lane & 3;

    const int j0     = blockIdx.x * MTILE;
    const int kb     = blockIdx.y;
    const int kbase0 = kb * KPER;
    const int jr     = j0 + warp * 16 + g;

    // cp.async coords:
    //   A16 tile: 16 rows x 128 halves = 256 x 16B chunks -> 1 chunk/thread
    //   G tile:   64 rows x  16 halves = 128 x 16B chunks -> tid<128, 1 chunk
    const int rowA = tid >> 4, chA = tid & 15;
    const int rowG = tid >> 1, chG = tid & 1;

    // ldmatrix per-lane base offsets (R8-proven A .trans, R10-proven G)
    const int l7   = lane & 7;
    const int l8   = lane & 8;
    const int l16h = (lane & 16) >> 1;
    const uint32_t aOffA = (uint32_t)((l7 + l16h) * AS_PITCH_H + warp * 16 + l8) * 2;
    const uint32_t aOffG = (uint32_t)((l16h + l7) * GS_PITCH_H + l8) * 2;

    float acc[8][4];
    #pragma unroll
    for (int nb = 0; nb < 8; ++nb)
        #pragma unroll
        for (int q = 0; q < 4; ++q) acc[nb][q] = 0.f;

    auto load_stage = [&](int st, int buf) {
        const int kst = kbase0 + st * KTILE;
        const uint32_t dA = sbase + (uint32_t)buf * BUF_BYTES;
        const uint32_t dG = dA + AS_BYTES;
        cp_async16(dA + (uint32_t)(rowA * AS_PITCH_H + chA * 8) * 2,
                   g_A16 + (size_t)(kst + rowA) * NF + j0 + chA * 8);
        if (tid < 128)
            cp_async16(dG + (uint32_t)(rowG * GS_PITCH_H + chG * 8) * 2,
                       g_GT + (size_t)rowG * NF + kst + chG * 8);
        CP_COMMIT();
    };

    load_stage(0, 0);
    load_stage(1, 1);
    load_stage(2, 2);
    load_stage(3, 3);
    load_stage(4, 4);

    for (int st = 0; st < NSTAGES; ++st) {
        const int buf = st % 6;
        // groups younger than st pending after wait: min(4, NSTAGES-1-st)
        if      (st <  NSTAGES - 4) CP_WAIT(4);
        else if (st == NSTAGES - 4) CP_WAIT(3);
        else if (st == NSTAGES - 3) CP_WAIT(2);
        else if (st == NSTAGES - 2) CP_WAIT(1);
        else                        CP_WAIT(0);
        __syncthreads();

        // prefetch into buffer consumed at stage st-1 (safe: sync above)
        if (st + 5 < NSTAGES) load_stage(st + 5, (st + 5) % 6);

        const uint32_t bA = sbase + (uint32_t)buf * BUF_BYTES + aOffA;
        const uint32_t bG = sbase + (uint32_t)buf * BUF_BYTES + AS_BYTES + aOffG;

        uint32_t af0, af1, af2, af3;
        LDSM_X4_T(af0, af1, af2, af3, bA);

        #pragma unroll
        for (int q = 0; q < 4; ++q) {
            uint32_t b0, b1, b2, b3;
            LDSM_X4(b0, b1, b2, b3, bG + (uint32_t)(q * 16 * GS_PITCH_H) * 2);
            asm volatile(
                "mma.sync.aligned.m16n8k16.row.col.f32.f16.f16.f32 "
                "{%0,%1,%2,%3}, {%4,%5,%6,%7}, {%8,%9}, {%0,%1,%2,%3};\n"
                : "+f"(acc[2*q][0]), "+f"(acc[2*q][1]),
                  "+f"(acc[2*q][2]), "+f"(acc[2*q][3])
                : "r"(af0), "r"(af1), "r"(af2), "r"(af3),
                  "r"(b0), "r"(b1));
            asm volatile(
                "mma.sync.aligned.m16n8k16.row.col.f32.f16.f16.f32 "
                "{%0,%1,%2,%3}, {%4,%5,%6,%7}, {%8,%9}, {%0,%1,%2,%3};\n"
                : "+f"(acc[2*q+1][0]), "+f"(acc[2*q+1][1]),
                  "+f"(acc[2*q+1][2]), "+f"(acc[2*q+1][3])
                : "r"(af0), "r"(af1), "r"(af2), "r"(af3),
                  "r"(b2), "r"(b3));
        }
    }

    float* P = g_Ppart + (size_t)kb * NF * CDIM;
    #pragma unroll
    for (int nb = 0; nb < 8; ++nb) {
        int cc = nb * 8 + 2 * t4;
        *reinterpret_cast<float2*>(&P[(size_t)jr * CDIM + cc]) =
            make_float2(acc[nb][0], acc[nb][1]);
        *reinterpret_cast<float2*>(&P[(size_t)(jr + 8) * CDIM + cc]) =
            make_float2(acc[nb][2], acc[nb][3]);
    }
}

// ------------------------------------------------------------- K4: epilogue --
__global__ void k4_epilogue(const float* __restrict__ b_gcn,
                            const float* __restrict__ Wout,
                            const float* __restrict__ bout,
                            float* __restrict__ out) {
    __shared__ float hs[160];
    __shared__ float Ws[2560];
    const int n = blockIdx.x;
    const int b = blockIdx.y;
    const int t = threadIdx.x;

    for (int q = t; q < 2560; q += 160) Ws[q] = Wout[q];

    const int f  = t / 16;
    const int o1 = t % 16;
    const int j  = n * 10 + f;
    const int c  = b * 16 + o1;

    float p = 0.f;
    #pragma unroll
    for (int s = 0; s < KSPLIT; ++s)
        p += g_Ppart[((size_t)s * NF + j) * CDIM + c];
    if (g_diagfix[j] != 0.f)                      // self-loop weight 1 on zero diag
        p += g_dinv[j] * g_H0T[c * NF + j];
    float h = g_dinv[j] * p + b_gcn[o1];
    hs[t] = fmaxf(h, 0.f);
    __syncthreads();

    if (t < 16) {
        float acc = bout[t];
        #pragma unroll 8
        for (int q = 0; q < 160; ++q) acc += hs[q] * Ws[q * 16 + t];
        out[((size_t)b * 1024 + n) * 16 + t] = acc;
    }
}

// ------------------------------------------------------------------ launch ---
extern "C" void kernel_launch(void* const* d_in, const int* in_sizes, int n_in,
                              void* d_out, int out_size) {
    const float* x        = (const float*)d_in[0];  // (4,1024,10,16)
    const float* supports = (const float*)d_in[3];  // (10240,10240)
    const float* W_gcn    = (const float*)d_in[6];  // (16,16)
    const float* b_gcn    = (const float*)d_in[7];  // (16,)
    const float* W_out    = (const float*)d_in[8];  // (160,16)
    const float* b_out    = (const float*)d_in[9];  // (16,)
    float* out = (float*)d_out;

    static int smem_set = 0;
    if (!smem_set) {
        cudaFuncSetAttribute(k3_gemm, cudaFuncAttributeMaxDynamicSharedMemorySize,
                             SMEM_TOTAL);
        smem_set = 1;
    }

    k1_a16_deg<<<dim3(NF / 1024, 80), 256>>>(supports);    // launch 1 (single wave)
    k2a_dinv<<<NF / 256, 256>>>(supports);                 // launch 2
    k0b_h0_gt<<<NF / 256, 256>>>(x, W_gcn);                // launch 3
    k3_gemm<<<dim3(NF / MTILE, KSPLIT), 256, SMEM_TOTAL>>>();  // launch 4 (profiled)
    k4_epilogue<<<dim3(1024, 4), 160>>>(b_gcn, W_out, b_out, out);
}

// round 14
// speedup vs baseline: 1.0468x; 1.0468x over previous
#include <cuda_runtime.h>
#include <cuda_fp16.h>
#include <cstdint>

#define NF    10240
#define CDIM  64      // B*DOUT = 4*16 packed batch-output columns
#define KSPLIT 5
#define KPER  (NF / KSPLIT)   // 2048
#define MTILE 128
#define KTILE 16
#define NSTAGES (KPER / KTILE)   // 128
#define NBUF  4
#define AS_PITCH 132     // fp32 words per A smem row (conflict-free: 8*t4+g distinct)
#define GS_PITCH_H 24    // halves per G smem row (LDSM word offsets distinct mod 32)
#define AS_BYTES (KTILE * AS_PITCH * 4)   // 8448
#define GS_BYTES (CDIM * GS_PITCH_H * 2)  // 3072
#define BUF_BYTES (AS_BYTES + GS_BYTES)   // 11520
#define SMEM_TOTAL (NBUF * BUF_BYTES)     // 46080 -> 4 CTAs/SM

// -------- device scratch (allocation-free rule: static __device__ arrays) ----
__device__ __align__(256) float  g_H0T[CDIM * NF];        // H0^T fp32 [c][i]
__device__ __align__(256) float  g_degPart[80 * NF];
__device__ float  g_dinv[NF];
__device__ float  g_diagfix[NF];
__device__ __align__(256) __half g_GT[CDIM * NF];         // G^T fp16 [c][i]
__device__ __align__(256) float  g_Ppart[KSPLIT * NF * CDIM];

// ----------- K1: deg column partials (R12-proven: 63.3us, 84% DRAM) ---------
__global__ __launch_bounds__(256, 6) void k1_degpart(const float* __restrict__ S) {
    int j4 = blockIdx.x * 1024 + threadIdx.x * 4;
    int r  = blockIdx.y;
    const float* p = S + (size_t)r * 128 * NF + j4;
    float4 acc = make_float4(0.f, 0.f, 0.f, 0.f);
    #pragma unroll 4
    for (int it = 0; it < 128; ++it) {
        float4 v = *reinterpret_cast<const float4*>(p);
        acc.x += v.x; acc.y += v.y; acc.z += v.z; acc.w += v.w;
        p += NF;
    }
    *reinterpret_cast<float4*>(&g_degPart[r * NF + j4]) = acc;
}

// ------------------------------------------------------- K2a: dinv + diagfix --
__global__ void k2a_dinv(const float* __restrict__ S) {
    int j = blockIdx.x * 256 + threadIdx.x;
    float s = 0.f;
    #pragma unroll 8
    for (int r = 0; r < 80; ++r) s += g_degPart[r * NF + j];
    float dv  = S[(size_t)j * NF + j];
    float fix = (dv == 0.0f) ? 1.0f : 0.0f;   // add_remaining_self_loops
    s += fix;
    g_diagfix[j] = fix;
    g_dinv[j] = (s > 0.f) ? rsqrtf(s) : 0.f;
}

// ------------------------------------- K0b: H0^T (fp32) + G^T (fp16, fused) --
__global__ void k0b_h0_gt(const float* __restrict__ x, const float* __restrict__ Wg) {
    __shared__ float W[256];
    if (threadIdx.x < 256) W[threadIdx.x] = Wg[threadIdx.x];
    __syncthreads();
    int i = blockIdx.x * 256 + threadIdx.x;
    float dv = g_dinv[i];
    #pragma unroll
    for (int b = 0; b < 4; ++b) {
        float xv[16];
        const float4* px = reinterpret_cast<const float4*>(x + ((size_t)b * NF + i) * 16);
        #pragma unroll
        for (int qd = 0; qd < 4; ++qd) {
            float4 v = px[qd];
            xv[qd*4+0] = v.x; xv[qd*4+1] = v.y; xv[qd*4+2] = v.z; xv[qd*4+3] = v.w;
        }
        #pragma unroll
        for (int o = 0; o < 16; ++o) {
            float s = 0.f;
            #pragma unroll
            for (int d = 0; d < 16; ++d) s += xv[d] * W[d * 16 + o];
            int c = b * 16 + o;
            g_H0T[c * NF + i] = s;
            g_GT[c * NF + i]  = __float2half_rn(dv * s);
        }
    }
}

// --------------------------------------------------------------- K3: GEMM ----
// P[j,c] = sum_i A[i,j]*G[i,c]; A fp32 cp.async (pack in-loop), G fp16 LDSM.
// R10-proven config: 4-buf ring, one sync per stage, 4 CTAs/SM, 80.9us.
__device__ __forceinline__ uint32_t pack_f16x2(float lo, float hi) {
    __half2 h = __floats2half2_rn(lo, hi);
    return *reinterpret_cast<uint32_t*>(&h);
}
__device__ __forceinline__ void cp_async16(uint32_t dst, const void* src) {
    asm volatile("cp.async.cg.shared.global [%0], [%1], 16;\n" :: "r"(dst), "l"(src));
}
#define CP_COMMIT() asm volatile("cp.async.commit_group;\n" ::: "memory")
#define CP_WAIT(n)  asm volatile("cp.async.wait_group %0;\n" :: "n"(n) : "memory")
#define LDSM_X4(r0,r1,r2,r3,a) \
    asm volatile("ldmatrix.sync.aligned.m8n8.x4.shared.b16 {%0,%1,%2,%3},[%4];" \
        : "=r"(r0),"=r"(r1),"=r"(r2),"=r"(r3) : "r"(a))

__global__ __launch_bounds__(256, 4) void k3_gemm(const float* __restrict__ A) {
    extern __shared__ char smem[];
    const uint32_t sbase = (uint32_t)__cvta_generic_to_shared(smem);

    const int tid  = threadIdx.x;
    const int warp = tid >> 5;
    const int lane = tid & 31;
    const int g    = lane >> 2;
    const int t4   = lane & 3;

    const int j0     = blockIdx.x * MTILE;
    const int kb     = blockIdx.y;
    const int kbase0 = kb * KPER;
    const int jr     = j0 + warp * 16 + g;

    // cp.async coords: A = 16 rows x 32 chunks (2/thread), G = 64 rows x 2 chunks
    const int rowA = tid >> 5, offA = (tid & 31) * 4;   // warp per row, 2 passes
    const int rowG = tid >> 1, chG = tid & 1;           // tid < 128 only

    // ldmatrix per-lane base offset for G (non-trans, [n][k]) -- R8-proven form
    const int l7   = lane & 7;
    const int l8   = lane & 8;
    const int l16h = (lane & 16) >> 1;
    const uint32_t aOffG = (uint32_t)((l16h + l7) * GS_PITCH_H + l8) * 2;

    float acc[8][4];
    #pragma unroll
    for (int nb = 0; nb < 8; ++nb)
        #pragma unroll
        for (int q = 0; q < 4; ++q) acc[nb][q] = 0.f;

    auto load_stage = [&](int st, int buf) {
        const int kst = kbase0 + st * KTILE;
        const uint32_t dA = sbase + (uint32_t)buf * BUF_BYTES;
        const uint32_t dG = dA + AS_BYTES;
        #pragma unroll
        for (int p = 0; p < 2; ++p) {
            int r = rowA + p * 8;
            cp_async16(dA + (uint32_t)(r * AS_PITCH + offA) * 4,
                       A + (size_t)(kst + r) * NF + j0 + offA);
        }
        if (tid < 128)
            cp_async16(dG + (uint32_t)(rowG * GS_PITCH_H + chG * 8) * 2,
                       g_GT + (size_t)rowG * NF + kst + chG * 8);
        CP_COMMIT();
    };

    load_stage(0, 0);
    load_stage(1, 1);
    load_stage(2, 2);

    const int col = warp * 16 + g;

    for (int st = 0; st < NSTAGES; ++st) {
        const int buf = st & 3;
        // complete through stage st (group st); taper at tail
        if      (st <  NSTAGES - 2) CP_WAIT(2);
        else if (st == NSTAGES - 2) CP_WAIT(1);
        else                        CP_WAIT(0);
        __syncthreads();

        // prefetch into buffer consumed at stage st-1 (safe: sync above)
        if (st + 3 < NSTAGES) load_stage(st + 3, (st + 3) & 3);

        const float* as = reinterpret_cast<const float*>(smem + buf * BUF_BYTES);
        const uint32_t bG = sbase + (uint32_t)buf * BUF_BYTES + AS_BYTES + aOffG;

        // one k16 step (R5/R9-proven A mapping)
        const int kr = 2 * t4;
        float x0 = as[kr * AS_PITCH + col];
        float x1 = as[(kr + 1) * AS_PITCH + col];
        float x2 = as[kr * AS_PITCH + col + 8];
        float x3 = as[(kr + 1) * AS_PITCH + col + 8];
        float y0 = as[(kr + 8) * AS_PITCH + col];
        float y1 = as[(kr + 9) * AS_PITCH + col];
        float y2 = as[(kr + 8) * AS_PITCH + col + 8];
        float y3 = as[(kr + 9) * AS_PITCH + col + 8];
        uint32_t af0 = pack_f16x2(x0, x1);   // (j=g,   k, k+1)
        uint32_t af1 = pack_f16x2(x2, x3);   // (j=g+8, k, k+1)
        uint32_t af2 = pack_f16x2(y0, y1);   // (j=g,   k+8, k+9)
        uint32_t af3 = pack_f16x2(y2, y3);   // (j=g+8, k+8, k+9)

        #pragma unroll
        for (int q = 0; q < 4; ++q) {        // B via LDSM (R8-proven)
            uint32_t b0, b1, b2, b3;
            LDSM_X4(b0, b1, b2, b3, bG + (uint32_t)(q * 16 * GS_PITCH_H) * 2);
            asm volatile(
                "mma.sync.aligned.m16n8k16.row.col.f32.f16.f16.f32 "
                "{%0,%1,%2,%3}, {%4,%5,%6,%7}, {%8,%9}, {%0,%1,%2,%3};\n"
                : "+f"(acc[2*q][0]), "+f"(acc[2*q][1]),
                  "+f"(acc[2*q][2]), "+f"(acc[2*q][3])
                : "r"(af0), "r"(af1), "r"(af2), "r"(af3),
                  "r"(b0), "r"(b1));
            asm volatile(
                "mma.sync.aligned.m16n8k16.row.col.f32.f16.f16.f32 "
                "{%0,%1,%2,%3}, {%4,%5,%6,%7}, {%8,%9}, {%0,%1,%2,%3};\n"
                : "+f"(acc[2*q+1][0]), "+f"(acc[2*q+1][1]),
                  "+f"(acc[2*q+1][2]), "+f"(acc[2*q+1][3])
                : "r"(af0), "r"(af1), "r"(af2), "r"(af3),
                  "r"(b2), "r"(b3));
        }
    }

    float* P = g_Ppart + (size_t)kb * NF * CDIM;
    #pragma unroll
    for (int nb = 0; nb < 8; ++nb) {
        int cc = nb * 8 + 2 * t4;
        *reinterpret_cast<float2*>(&P[(size_t)jr * CDIM + cc]) =
            make_float2(acc[nb][0], acc[nb][1]);
        *reinterpret_cast<float2*>(&P[(size_t)(jr + 8) * CDIM + cc]) =
            make_float2(acc[nb][2], acc[nb][3]);
    }
}

// ------------------------------------------------------------- K4: epilogue --
__global__ void k4_epilogue(const float* __restrict__ b_gcn,
                            const float* __restrict__ Wout,
                            const float* __restrict__ bout,
                            float* __restrict__ out) {
    __shared__ float hs[160];
    __shared__ float Ws[2560];
    const int n = blockIdx.x;
    const int b = blockIdx.y;
    const int t = threadIdx.x;

    for (int q = t; q < 2560; q += 160) Ws[q] = Wout[q];

    const int f  = t / 16;
    const int o1 = t % 16;
    const int j  = n * 10 + f;
    const int c  = b * 16 + o1;

    float p = 0.f;
    #pragma unroll
    for (int s = 0; s < KSPLIT; ++s)
        p += g_Ppart[((size_t)s * NF + j) * CDIM + c];
    if (g_diagfix[j] != 0.f)                      // self-loop weight 1 on zero diag
        p += g_dinv[j] * g_H0T[c * NF + j];
    float h = g_dinv[j] * p + b_gcn[o1];
    hs[t] = fmaxf(h, 0.f);
    __syncthreads();

    if (t < 16) {
        float acc = bout[t];
        #pragma unroll 8
        for (int q = 0; q < 160; ++q) acc += hs[q] * Ws[q * 16 + t];
        out[((size_t)b * 1024 + n) * 16 + t] = acc;
    }
}

// ------------------------------------------------------------------ launch ---
extern "C" void kernel_launch(void* const* d_in, const int* in_sizes, int n_in,
                              void* d_out, int out_size) {
    const float* x        = (const float*)d_in[0];  // (4,1024,10,16)
    const float* supports = (const float*)d_in[3];  // (10240,10240)
    const float* W_gcn    = (const float*)d_in[6];  // (16,16)
    const float* b_gcn    = (const float*)d_in[7];  // (16,)
    const float* W_out    = (const float*)d_in[8];  // (160,16)
    const float* b_out    = (const float*)d_in[9];  // (16,)
    float* out = (float*)d_out;

    static int smem_set = 0;
    if (!smem_set) {
        cudaFuncSetAttribute(k3_gemm, cudaFuncAttributeMaxDynamicSharedMemorySize,
                             SMEM_TOTAL);
        smem_set = 1;
    }

    k1_degpart<<<dim3(NF / 1024, 80), 256>>>(supports);    // launch 1 (63.3us proven)
    k2a_dinv<<<NF / 256, 256>>>(supports);                 // launch 2
    k0b_h0_gt<<<NF / 256, 256>>>(x, W_gcn);                // launch 3
    k3_gemm<<<dim3(NF / MTILE, KSPLIT), 256, SMEM_TOTAL>>>(supports);  // launch 4 (80.9us proven)
    k4_epilogue<<<dim3(1024, 4), 160>>>(b_gcn, W_out, b_out, out);
}